// round 5
// baseline (speedup 1.0000x reference)
#include <cuda_runtime.h>
#include <cuda_bf16.h>
#include <math.h>

// ---------------------------------------------------------------------------
// SearchNet: cosine similarity top-k
//   query [512] f32, database [N,512] f32 (N=500000), top_num=100
//   out: [values(K) | indices-as-float(K)] where K = out_size/2
//
// Pipeline (5 kernels):
//   init      : zero hist/counters + normalize query
//   sims      : fused dot+norm -> sortable keys (DRAM-bound, no atomics)
//   hist+scan : smem-aggregated histogram; LAST block computes threshold bin
//   collect   : gather candidates with top-11-bit bin >= g_sel1 (MLP=4)
//   final     : exact rank among candidates (shared-mem staged), write top-K
// ---------------------------------------------------------------------------

#define D 512
#define MAXN (1 << 20)        // >= 500000
#define CAND_CAP 16384
#define SH_CAP 6144           // candidates staged in shared memory (48KB)

__device__ unsigned int g_keys[MAXN];
__device__ float        g_qn[D];
__device__ unsigned int g_hist1[2048];
__device__ unsigned int g_histdone;
__device__ unsigned int g_sel1;
__device__ unsigned int g_ncand;
__device__ unsigned int g_cand_key[CAND_CAP];
__device__ unsigned int g_cand_idx[CAND_CAP];

// float -> order-preserving uint
__device__ __forceinline__ unsigned int f2key(float f) {
    unsigned int u = __float_as_uint(f);
    return (u & 0x80000000u) ? ~u : (u | 0x80000000u);
}
__device__ __forceinline__ float key2f(unsigned int k) {
    unsigned int u = (k & 0x80000000u) ? (k ^ 0x80000000u) : ~k;
    return __uint_as_float(u);
}

// ---------------- init: zero scratch + normalize query ---------------------
__global__ __launch_bounds__(1024) void init_kernel(const float* __restrict__ q) {
    __shared__ float sh[512];
    __shared__ float inv;
    int t = threadIdx.x;
    g_hist1[t] = 0;
    g_hist1[t + 1024] = 0;
    if (t == 0) { g_ncand = 0; g_histdone = 0; }
    float v = 0.f;
    if (t < D) { v = q[t]; sh[t] = v * v; }
    __syncthreads();
    for (int s = D / 2; s > 0; s >>= 1) {
        if (t < s) sh[t] += sh[t + s];
        __syncthreads();
    }
    if (t == 0) inv = 1.0f / fmaxf(sqrtf(sh[0]), 1e-8f);
    __syncthreads();
    if (t < D) g_qn[t] = v * inv;
}

// ---------------- fused dot + row-norm, 2 rows per warp --------------------
__global__ __launch_bounds__(256) void sims_kernel(const float* __restrict__ db, int N) {
    int warp = (blockIdx.x * blockDim.x + threadIdx.x) >> 5;
    int lane = threadIdx.x & 31;
    int r0 = warp * 2;
    if (r0 >= N) return;
    bool has1 = (r0 + 1) < N;

    const float4* q4 = (const float4*)g_qn;
    float4 q0 = q4[lane];
    float4 q1 = q4[lane + 32];
    float4 q2 = q4[lane + 64];
    float4 q3 = q4[lane + 96];

    const float4* rowA = (const float4*)(db + (size_t)r0 * D);
    const float4* rowB = (const float4*)(db + (size_t)(r0 + (has1 ? 1 : 0)) * D);

    // front-batch 8 independent DRAM loads
    float4 a0 = rowA[lane];
    float4 a1 = rowA[lane + 32];
    float4 a2 = rowA[lane + 64];
    float4 a3 = rowA[lane + 96];
    float4 b0 = rowB[lane];
    float4 b1 = rowB[lane + 32];
    float4 b2 = rowB[lane + 64];
    float4 b3 = rowB[lane + 96];

    float dotA = a0.x*q0.x + a0.y*q0.y + a0.z*q0.z + a0.w*q0.w
               + a1.x*q1.x + a1.y*q1.y + a1.z*q1.z + a1.w*q1.w
               + a2.x*q2.x + a2.y*q2.y + a2.z*q2.z + a2.w*q2.w
               + a3.x*q3.x + a3.y*q3.y + a3.z*q3.z + a3.w*q3.w;
    float n2A  = a0.x*a0.x + a0.y*a0.y + a0.z*a0.z + a0.w*a0.w
               + a1.x*a1.x + a1.y*a1.y + a1.z*a1.z + a1.w*a1.w
               + a2.x*a2.x + a2.y*a2.y + a2.z*a2.z + a2.w*a2.w
               + a3.x*a3.x + a3.y*a3.y + a3.z*a3.z + a3.w*a3.w;
    float dotB = b0.x*q0.x + b0.y*q0.y + b0.z*q0.z + b0.w*q0.w
               + b1.x*q1.x + b1.y*q1.y + b1.z*q1.z + b1.w*q1.w
               + b2.x*q2.x + b2.y*q2.y + b2.z*q2.z + b2.w*q2.w
               + b3.x*q3.x + b3.y*q3.y + b3.z*q3.z + b3.w*q3.w;
    float n2B  = b0.x*b0.x + b0.y*b0.y + b0.z*b0.z + b0.w*b0.w
               + b1.x*b1.x + b1.y*b1.y + b1.z*b1.z + b1.w*b1.w
               + b2.x*b2.x + b2.y*b2.y + b2.z*b2.z + b2.w*b2.w
               + b3.x*b3.x + b3.y*b3.y + b3.z*b3.z + b3.w*b3.w;

#pragma unroll
    for (int off = 16; off; off >>= 1) {
        dotA += __shfl_down_sync(0xFFFFFFFFu, dotA, off);
        n2A  += __shfl_down_sync(0xFFFFFFFFu, n2A, off);
        dotB += __shfl_down_sync(0xFFFFFFFFu, dotB, off);
        n2B  += __shfl_down_sync(0xFFFFFFFFu, n2B, off);
    }
    if (lane == 0) {
        g_keys[r0] = f2key(dotA / fmaxf(sqrtf(n2A), 1e-8f));
        if (has1) g_keys[r0 + 1] = f2key(dotB / fmaxf(sqrtf(n2B), 1e-8f));
    }
}

// ---------------- histogram + (last block) threshold scan ------------------
__global__ __launch_bounds__(256) void hist_kernel(int N, int K) {
    __shared__ unsigned int sh[2048];
    int t = threadIdx.x;
    for (int i = t; i < 2048; i += blockDim.x) sh[i] = 0;
    __syncthreads();
    int n4 = N >> 2;
    const uint4* k4 = (const uint4*)g_keys;
    for (int i = blockIdx.x * blockDim.x + t; i < n4; i += gridDim.x * blockDim.x) {
        uint4 k = k4[i];
        atomicAdd(&sh[k.x >> 21], 1u);
        atomicAdd(&sh[k.y >> 21], 1u);
        atomicAdd(&sh[k.z >> 21], 1u);
        atomicAdd(&sh[k.w >> 21], 1u);
    }
    if (blockIdx.x == 0) {
        for (int i = (n4 << 2) + t; i < N; i += blockDim.x)
            atomicAdd(&sh[g_keys[i] >> 21], 1u);
    }
    __syncthreads();
    for (int i = t; i < 2048; i += blockDim.x)
        if (sh[i]) atomicAdd(&g_hist1[i], sh[i]);

    // ---- last finishing block computes the threshold bin ----
    __shared__ bool last;
    __threadfence();
    if (t == 0) last = (atomicAdd(&g_histdone, 1u) == gridDim.x - 1);
    __syncthreads();
    if (!last) return;

    // thread t owns 8 descending bins: base, base-1, ..., base-7
    int base = 2047 - t * 8;
    unsigned int c[8];
    unsigned int s = 0;
#pragma unroll
    for (int j = 0; j < 8; j++) { c[j] = g_hist1[base - j]; s += c[j]; }

    // inclusive warp scan of chunk sums in thread order (descending bins)
    int lane = t & 31;
    int w = t >> 5;
    unsigned int incl = s;
#pragma unroll
    for (int off = 1; off < 32; off <<= 1) {
        unsigned int v = __shfl_up_sync(0xFFFFFFFFu, incl, off);
        if (lane >= off) incl += v;
    }
    __shared__ unsigned int wsum[8];
    if (lane == 31) wsum[w] = incl;
    __syncthreads();
    if (t < 8) {
        unsigned int v = wsum[t];
#pragma unroll
        for (int off = 1; off < 8; off <<= 1) {
            unsigned int u = __shfl_up_sync(0xFFu, v, off);
            if (t >= off) v += u;
        }
        wsum[t] = v;
    }
    __syncthreads();
    unsigned int before = incl - s + (w > 0 ? wsum[w - 1] : 0u);
    unsigned int after  = before + s;
    unsigned int need = (unsigned int)K;
    if (before < need && after >= need) {     // unique crossing thread (s > 0)
        unsigned int cum = before;
#pragma unroll
        for (int j = 0; j < 8; j++) {
            cum += c[j];
            if (cum >= need) { g_sel1 = (unsigned int)(base - j); break; }
        }
    }
}

// ---------------- collect: 4 front-batched uint4 loads per thread ----------
__global__ __launch_bounds__(256) void collect_kernel(int N) {
    unsigned int sel = g_sel1;
    int n4 = N >> 2;
    const uint4* k4 = (const uint4*)g_keys;
    int stride = blockDim.x;
    int base0 = blockIdx.x * stride * 4 + threadIdx.x;

    uint4 kk[4];
    int   idx[4];
    int cnt = 0;
#pragma unroll
    for (int u = 0; u < 4; u++) {
        int i = base0 + u * stride;
        if (i < n4) { kk[cnt] = k4[i]; idx[cnt] = i << 2; cnt++; }
    }
#pragma unroll
    for (int u = 0; u < 4; u++) {
        if (u >= cnt) break;
        uint4 k = kk[u];
        int b = idx[u];
        if ((k.x >> 21) >= sel) {
            unsigned int p = atomicAdd(&g_ncand, 1u);
            if (p < CAND_CAP) { g_cand_key[p] = k.x; g_cand_idx[p] = b; }
        }
        if ((k.y >> 21) >= sel) {
            unsigned int p = atomicAdd(&g_ncand, 1u);
            if (p < CAND_CAP) { g_cand_key[p] = k.y; g_cand_idx[p] = b + 1; }
        }
        if ((k.z >> 21) >= sel) {
            unsigned int p = atomicAdd(&g_ncand, 1u);
            if (p < CAND_CAP) { g_cand_key[p] = k.z; g_cand_idx[p] = b + 2; }
        }
        if ((k.w >> 21) >= sel) {
            unsigned int p = atomicAdd(&g_ncand, 1u);
            if (p < CAND_CAP) { g_cand_key[p] = k.w; g_cand_idx[p] = b + 3; }
        }
    }
    // scalar tail
    if (blockIdx.x == 0) {
        for (int i = (n4 << 2) + threadIdx.x; i < N; i += blockDim.x) {
            unsigned int key = g_keys[i];
            if ((key >> 21) >= sel) {
                unsigned int p = atomicAdd(&g_ncand, 1u);
                if (p < CAND_CAP) { g_cand_key[p] = key; g_cand_idx[p] = (unsigned int)i; }
            }
        }
    }
}

// ---------------- rank candidates, write top-K (jax tie-break: lower idx) --
__global__ __launch_bounds__(1024) void final_kernel(float* __restrict__ out, int K) {
    __shared__ unsigned int sk[SH_CAP];
    __shared__ unsigned int si[SH_CAP];
    unsigned int n = g_ncand;
    if (n > CAND_CAP) n = CAND_CAP;
    bool use_sh = (n <= SH_CAP);
    if (use_sh) {
        for (unsigned int i = threadIdx.x; i < n; i += blockDim.x) {
            sk[i] = g_cand_key[i];
            si[i] = g_cand_idx[i];
        }
        __syncthreads();
    }
    for (unsigned int c = threadIdx.x; c < n; c += blockDim.x) {
        unsigned int key = use_sh ? sk[c] : g_cand_key[c];
        unsigned int idx = use_sh ? si[c] : g_cand_idx[c];
        unsigned int rank = 0;
        if (use_sh) {
            for (unsigned int j = 0; j < n; j++) {
                unsigned int kj = sk[j];
                if (kj > key || (kj == key && si[j] < idx)) rank++;
            }
        } else {
            for (unsigned int j = 0; j < n; j++) {
                unsigned int kj = g_cand_key[j];
                if (kj > key || (kj == key && g_cand_idx[j] < idx)) rank++;
            }
        }
        if (rank < (unsigned int)K) {
            out[rank]     = key2f(key);
            out[K + rank] = (float)idx;
        }
    }
}

// ---------------------------------------------------------------------------
extern "C" void kernel_launch(void* const* d_in, const int* in_sizes, int n_in,
                              void* d_out, int out_size) {
    const float* q  = (const float*)d_in[0];
    const float* db = (const float*)d_in[1];
    int N = in_sizes[1] / D;
    int K = out_size / 2;   // values + indices
    float* out = (float*)d_out;

    int n4 = N / 4;
    int histBlocks = (n4 + 2 * 256 - 1) / (2 * 256);     // ~2 uint4/thread
    if (histBlocks > 1024) histBlocks = 1024;
    int collectBlocks = (n4 + 4 * 256 - 1) / (4 * 256);  // 4 uint4/thread
    int simsBlocks = (N + 15) / 16;                      // 8 warps, 2 rows/warp

    init_kernel<<<1, 1024>>>(q);
    sims_kernel<<<simsBlocks, 256>>>(db, N);
    hist_kernel<<<histBlocks, 256>>>(N, K);
    collect_kernel<<<collectBlocks, 256>>>(N);
    final_kernel<<<1, 1024>>>(out, K);
}

// round 6
// speedup vs baseline: 1.0052x; 1.0052x over previous
#include <cuda_runtime.h>
#include <cuda_bf16.h>
#include <math.h>

// ---------------------------------------------------------------------------
// SearchNet: cosine similarity top-k
//   query [512] f32, database [N,512] f32 (N=500000), top_num=100
//   out: [values(K) | indices-as-float(K)] where K = out_size/2
//
// Pipeline (3 kernels):
//   sims          : dot(q_raw,d)/|d| -> sortable keys. Ordering is invariant
//                   under the positive constant 1/|q|, so no query prenorm.
//   hist+scan     : smem-aggregated 2048-bin histogram of top 11 key bits;
//                   LAST finishing block finds threshold bin, then re-zeroes
//                   the histogram + done counter (self-cleaning for replays).
//   collect+final : gather candidates with bin >= g_sel1; LAST finishing
//                   block computes |q|, ranks candidates exactly (smem),
//                   writes top-K values (scaled by 1/|q|) + indices, resets.
//
// __device__ globals are zero-initialized at load; every kernel restores the
// zeroed invariant before exiting, so graph replays see a clean state.
// ---------------------------------------------------------------------------

#define D 512
#define MAXN (1 << 20)        // >= 500000
#define CAND_CAP 16384
#define SH_CAP 6144           // candidates staged in shared memory (48KB)

__device__ unsigned int g_keys[MAXN];
__device__ unsigned int g_hist1[2048];    // zero at load; re-zeroed each call
__device__ unsigned int g_histdone;       // zero at load; re-zeroed each call
__device__ unsigned int g_sel1;
__device__ unsigned int g_ncand;          // zero at load; re-zeroed each call
__device__ unsigned int g_cfdone;         // zero at load; re-zeroed each call
__device__ unsigned int g_cand_key[CAND_CAP];
__device__ unsigned int g_cand_idx[CAND_CAP];

// float -> order-preserving uint
__device__ __forceinline__ unsigned int f2key(float f) {
    unsigned int u = __float_as_uint(f);
    return (u & 0x80000000u) ? ~u : (u | 0x80000000u);
}
__device__ __forceinline__ float key2f(unsigned int k) {
    unsigned int u = (k & 0x80000000u) ? (k ^ 0x80000000u) : ~k;
    return __uint_as_float(u);
}

// ---------------- sims: dot(q,d)/|d|, 2 rows per warp ----------------------
__global__ __launch_bounds__(256) void sims_kernel(const float* __restrict__ db,
                                                   const float* __restrict__ q,
                                                   int N) {
    int warp = (blockIdx.x * blockDim.x + threadIdx.x) >> 5;
    int lane = threadIdx.x & 31;
    int r0 = warp * 2;
    if (r0 >= N) return;
    bool has1 = (r0 + 1) < N;

    const float4* q4 = (const float4*)q;
    float4 q0 = __ldg(&q4[lane]);
    float4 q1 = __ldg(&q4[lane + 32]);
    float4 q2 = __ldg(&q4[lane + 64]);
    float4 q3 = __ldg(&q4[lane + 96]);

    const float4* rowA = (const float4*)(db + (size_t)r0 * D);
    const float4* rowB = (const float4*)(db + (size_t)(r0 + (has1 ? 1 : 0)) * D);

    // front-batch 8 independent DRAM loads
    float4 a0 = rowA[lane];
    float4 a1 = rowA[lane + 32];
    float4 a2 = rowA[lane + 64];
    float4 a3 = rowA[lane + 96];
    float4 b0 = rowB[lane];
    float4 b1 = rowB[lane + 32];
    float4 b2 = rowB[lane + 64];
    float4 b3 = rowB[lane + 96];

    float dotA = a0.x*q0.x + a0.y*q0.y + a0.z*q0.z + a0.w*q0.w
               + a1.x*q1.x + a1.y*q1.y + a1.z*q1.z + a1.w*q1.w
               + a2.x*q2.x + a2.y*q2.y + a2.z*q2.z + a2.w*q2.w
               + a3.x*q3.x + a3.y*q3.y + a3.z*q3.z + a3.w*q3.w;
    float n2A  = a0.x*a0.x + a0.y*a0.y + a0.z*a0.z + a0.w*a0.w
               + a1.x*a1.x + a1.y*a1.y + a1.z*a1.z + a1.w*a1.w
               + a2.x*a2.x + a2.y*a2.y + a2.z*a2.z + a2.w*a2.w
               + a3.x*a3.x + a3.y*a3.y + a3.z*a3.z + a3.w*a3.w;
    float dotB = b0.x*q0.x + b0.y*q0.y + b0.z*q0.z + b0.w*q0.w
               + b1.x*q1.x + b1.y*q1.y + b1.z*q1.z + b1.w*q1.w
               + b2.x*q2.x + b2.y*q2.y + b2.z*q2.z + b2.w*q2.w
               + b3.x*q3.x + b3.y*q3.y + b3.z*q3.z + b3.w*q3.w;
    float n2B  = b0.x*b0.x + b0.y*b0.y + b0.z*b0.z + b0.w*b0.w
               + b1.x*b1.x + b1.y*b1.y + b1.z*b1.z + b1.w*b1.w
               + b2.x*b2.x + b2.y*b2.y + b2.z*b2.z + b2.w*b2.w
               + b3.x*b3.x + b3.y*b3.y + b3.z*b3.z + b3.w*b3.w;

#pragma unroll
    for (int off = 16; off; off >>= 1) {
        dotA += __shfl_down_sync(0xFFFFFFFFu, dotA, off);
        n2A  += __shfl_down_sync(0xFFFFFFFFu, n2A, off);
        dotB += __shfl_down_sync(0xFFFFFFFFu, dotB, off);
        n2B  += __shfl_down_sync(0xFFFFFFFFu, n2B, off);
    }
    if (lane == 0) {
        g_keys[r0] = f2key(dotA / fmaxf(sqrtf(n2A), 1e-8f));
        if (has1) g_keys[r0 + 1] = f2key(dotB / fmaxf(sqrtf(n2B), 1e-8f));
    }
}

// ---------------- histogram + (last block) threshold scan + self-clean -----
__global__ __launch_bounds__(256) void hist_kernel(int N, int K) {
    __shared__ unsigned int sh[2048];
    int t = threadIdx.x;
    for (int i = t; i < 2048; i += blockDim.x) sh[i] = 0;
    __syncthreads();
    int n4 = N >> 2;
    const uint4* k4 = (const uint4*)g_keys;
    for (int i = blockIdx.x * blockDim.x + t; i < n4; i += gridDim.x * blockDim.x) {
        uint4 k = k4[i];
        atomicAdd(&sh[k.x >> 21], 1u);
        atomicAdd(&sh[k.y >> 21], 1u);
        atomicAdd(&sh[k.z >> 21], 1u);
        atomicAdd(&sh[k.w >> 21], 1u);
    }
    if (blockIdx.x == 0) {
        for (int i = (n4 << 2) + t; i < N; i += blockDim.x)
            atomicAdd(&sh[g_keys[i] >> 21], 1u);
    }
    __syncthreads();
    for (int i = t; i < 2048; i += blockDim.x)
        if (sh[i]) atomicAdd(&g_hist1[i], sh[i]);

    // ---- last finishing block: threshold scan ----
    __shared__ bool last;
    __threadfence();
    if (t == 0) last = (atomicAdd(&g_histdone, 1u) == gridDim.x - 1);
    __syncthreads();
    if (!last) return;

    // thread t owns 8 descending bins: base, base-1, ..., base-7
    int base = 2047 - t * 8;
    unsigned int c[8];
    unsigned int s = 0;
#pragma unroll
    for (int j = 0; j < 8; j++) { c[j] = g_hist1[base - j]; s += c[j]; }

    int lane = t & 31;
    int w = t >> 5;
    unsigned int incl = s;
#pragma unroll
    for (int off = 1; off < 32; off <<= 1) {
        unsigned int v = __shfl_up_sync(0xFFFFFFFFu, incl, off);
        if (lane >= off) incl += v;
    }
    __shared__ unsigned int wsum[8];
    if (lane == 31) wsum[w] = incl;
    __syncthreads();
    if (t < 8) {
        unsigned int v = wsum[t];
#pragma unroll
        for (int off = 1; off < 8; off <<= 1) {
            unsigned int u = __shfl_up_sync(0xFFu, v, off);
            if (t >= off) v += u;
        }
        wsum[t] = v;
    }
    __syncthreads();
    unsigned int before = incl - s + (w > 0 ? wsum[w - 1] : 0u);
    unsigned int after  = before + s;
    unsigned int need = (unsigned int)K;
    if (before < need && after >= need) {     // unique crossing thread
        unsigned int cum = before;
#pragma unroll
        for (int j = 0; j < 8; j++) {
            cum += c[j];
            if (cum >= need) { g_sel1 = (unsigned int)(base - j); break; }
        }
    }
    __syncthreads();
    // self-clean for next graph replay (all reads of g_hist1 are done)
    for (int i = t; i < 2048; i += blockDim.x) g_hist1[i] = 0;
    if (t == 0) g_histdone = 0;
}

// ---------------- collect + (last block) final rank + self-clean -----------
__global__ __launch_bounds__(1024) void collect_final_kernel(
        const float* __restrict__ q, float* __restrict__ out, int N, int K) {
    unsigned int sel = g_sel1;
    int n4 = N >> 2;
    const uint4* k4 = (const uint4*)g_keys;
    for (int i = blockIdx.x * blockDim.x + threadIdx.x; i < n4;
         i += gridDim.x * blockDim.x) {
        uint4 k = k4[i];
        int base = i << 2;
        if ((k.x >> 21) >= sel) {
            unsigned int p = atomicAdd(&g_ncand, 1u);
            if (p < CAND_CAP) { g_cand_key[p] = k.x; g_cand_idx[p] = base; }
        }
        if ((k.y >> 21) >= sel) {
            unsigned int p = atomicAdd(&g_ncand, 1u);
            if (p < CAND_CAP) { g_cand_key[p] = k.y; g_cand_idx[p] = base + 1; }
        }
        if ((k.z >> 21) >= sel) {
            unsigned int p = atomicAdd(&g_ncand, 1u);
            if (p < CAND_CAP) { g_cand_key[p] = k.z; g_cand_idx[p] = base + 2; }
        }
        if ((k.w >> 21) >= sel) {
            unsigned int p = atomicAdd(&g_ncand, 1u);
            if (p < CAND_CAP) { g_cand_key[p] = k.w; g_cand_idx[p] = base + 3; }
        }
    }
    if (blockIdx.x == 0) {
        for (int i = (n4 << 2) + threadIdx.x; i < N; i += blockDim.x) {
            unsigned int key = g_keys[i];
            if ((key >> 21) >= sel) {
                unsigned int p = atomicAdd(&g_ncand, 1u);
                if (p < CAND_CAP) { g_cand_key[p] = key; g_cand_idx[p] = (unsigned int)i; }
            }
        }
    }

    // ---- last finishing block: exact rank + output ----
    __shared__ bool last;
    __threadfence();
    if (threadIdx.x == 0) last = (atomicAdd(&g_cfdone, 1u) == gridDim.x - 1);
    __syncthreads();
    if (!last) return;

    int t = threadIdx.x;
    int lane = t & 31;
    int w = t >> 5;

    // 1/|q| (512 elems over 1024 threads)
    __shared__ float qs[32];
    __shared__ float qinv;
    float acc = (t < D) ? q[t] * q[t] : 0.f;
#pragma unroll
    for (int off = 16; off; off >>= 1) acc += __shfl_down_sync(0xFFFFFFFFu, acc, off);
    if (lane == 0) qs[w] = acc;
    __syncthreads();
    if (t == 0) {
        float s = 0.f;
#pragma unroll
        for (int i = 0; i < 32; i++) s += qs[i];
        qinv = 1.0f / fmaxf(sqrtf(s), 1e-8f);
    }

    __shared__ unsigned int sk[SH_CAP];
    __shared__ unsigned int si[SH_CAP];
    unsigned int n = g_ncand;
    if (n > CAND_CAP) n = CAND_CAP;
    bool use_sh = (n <= SH_CAP);
    if (use_sh) {
        for (unsigned int i = t; i < n; i += blockDim.x) {
            sk[i] = g_cand_key[i];
            si[i] = g_cand_idx[i];
        }
    }
    __syncthreads();

    for (unsigned int c = t; c < n; c += blockDim.x) {
        unsigned int key = use_sh ? sk[c] : g_cand_key[c];
        unsigned int idx = use_sh ? si[c] : g_cand_idx[c];
        unsigned int rank = 0;
        if (use_sh) {
            for (unsigned int j = 0; j < n; j++) {
                unsigned int kj = sk[j];
                if (kj > key || (kj == key && si[j] < idx)) rank++;
            }
        } else {
            for (unsigned int j = 0; j < n; j++) {
                unsigned int kj = g_cand_key[j];
                if (kj > key || (kj == key && g_cand_idx[j] < idx)) rank++;
            }
        }
        if (rank < (unsigned int)K) {
            out[rank]     = key2f(key) * qinv;
            out[K + rank] = (float)idx;
        }
    }
    __syncthreads();
    if (t == 0) { g_ncand = 0; g_cfdone = 0; }   // self-clean for replay
}

// ---------------------------------------------------------------------------
extern "C" void kernel_launch(void* const* d_in, const int* in_sizes, int n_in,
                              void* d_out, int out_size) {
    const float* q  = (const float*)d_in[0];
    const float* db = (const float*)d_in[1];
    int N = in_sizes[1] / D;
    int K = out_size / 2;   // values + indices
    float* out = (float*)d_out;

    int n4 = N / 4;
    int histBlocks = (n4 + 255) / 256;            // ~1 uint4/thread (489 @ N=500k)
    if (histBlocks > 1024) histBlocks = 1024;
    int cfBlocks = (n4 + 1023) / 1024;            // 1024-thread blocks (123)
    if (cfBlocks > 1024) cfBlocks = 1024;
    int simsBlocks = (N + 15) / 16;               // 8 warps, 2 rows/warp

    sims_kernel<<<simsBlocks, 256>>>(db, q, N);
    hist_kernel<<<histBlocks, 256>>>(N, K);
    collect_final_kernel<<<cfBlocks, 1024>>>(q, out, N, K);
}

// round 8
// speedup vs baseline: 1.0179x; 1.0127x over previous
#include <cuda_runtime.h>
#include <cuda_bf16.h>
#include <math.h>

// ---------------------------------------------------------------------------
// SearchNet: cosine similarity top-k
//   query [512] f32, database [N,512] f32 (N=500000), top_num=100
//   out: [values(K) | indices-as-float(K)] where K = out_size/2
//
// Pipeline (2 kernels):
//   sims   : dot(q_raw,d)/|d| -> sortable keys (order invariant under 1/|q|).
//   select : ONE kernel with a software grid barrier. Residency proof:
//            grid = 296 blocks (2/SM on 148+ SMs), 256 thr, 32KB smem
//            (>=7 blocks/SM smem-limit, >=6 reg-limit) -> all blocks
//            co-resident with >3x margin, so the spin barrier is safe.
//            Phases: smem hist -> barrier -> per-block threshold scan ->
//            collect -> last-finishing block ranks in smem + writes + cleans.
//            Shared buffer reused: hist (phase1-2) then cand keys/idx (phase4).
// ---------------------------------------------------------------------------

#define D 512
#define MAXN (1 << 20)        // >= 500000
#define CAND_CAP 16384
#define SH_CAP 4096           // candidates staged in reused 32KB smem
#define SEL_BLOCKS 296        // 2 per SM; co-resident with large margin

__device__ unsigned int g_keys[MAXN];
__device__ unsigned int g_hist1[2048];              // zeroed at load + self-clean
__device__ unsigned int g_bar_count;
__device__ volatile unsigned int g_bar_gen;
__device__ unsigned int g_ncand;
__device__ unsigned int g_cfdone;
__device__ unsigned int g_cand_key[CAND_CAP];
__device__ unsigned int g_cand_idx[CAND_CAP];

// float -> order-preserving uint
__device__ __forceinline__ unsigned int f2key(float f) {
    unsigned int u = __float_as_uint(f);
    return (u & 0x80000000u) ? ~u : (u | 0x80000000u);
}
__device__ __forceinline__ float key2f(unsigned int k) {
    unsigned int u = (k & 0x80000000u) ? (k ^ 0x80000000u) : ~k;
    return __uint_as_float(u);
}

// grid-wide spin barrier: ONLY valid when all blocks are co-resident.
__device__ __forceinline__ void grid_barrier(int nblocks) {
    __syncthreads();
    if (threadIdx.x == 0) {
        unsigned int gen = g_bar_gen;
        __threadfence();
        if (atomicAdd(&g_bar_count, 1u) == (unsigned int)nblocks - 1) {
            g_bar_count = 0;
            __threadfence();
            g_bar_gen = gen + 1;
        } else {
            while (g_bar_gen == gen) __nanosleep(32);
        }
    }
    __syncthreads();
    __threadfence();
}

// ---------------- sims: dot(q,d)/|d|, 2 rows per warp ----------------------
__global__ __launch_bounds__(256) void sims_kernel(const float* __restrict__ db,
                                                   const float* __restrict__ q,
                                                   int N) {
    int warp = (blockIdx.x * blockDim.x + threadIdx.x) >> 5;
    int lane = threadIdx.x & 31;
    int r0 = warp * 2;
    if (r0 >= N) return;
    bool has1 = (r0 + 1) < N;

    const float4* q4 = (const float4*)q;
    float4 q0 = __ldg(&q4[lane]);
    float4 q1 = __ldg(&q4[lane + 32]);
    float4 q2 = __ldg(&q4[lane + 64]);
    float4 q3 = __ldg(&q4[lane + 96]);

    const float4* rowA = (const float4*)(db + (size_t)r0 * D);
    const float4* rowB = (const float4*)(db + (size_t)(r0 + (has1 ? 1 : 0)) * D);

    // front-batch 8 independent streaming DRAM loads (touch-once data)
    float4 a0 = __ldcs(&rowA[lane]);
    float4 a1 = __ldcs(&rowA[lane + 32]);
    float4 a2 = __ldcs(&rowA[lane + 64]);
    float4 a3 = __ldcs(&rowA[lane + 96]);
    float4 b0 = __ldcs(&rowB[lane]);
    float4 b1 = __ldcs(&rowB[lane + 32]);
    float4 b2 = __ldcs(&rowB[lane + 64]);
    float4 b3 = __ldcs(&rowB[lane + 96]);

    float dotA = a0.x*q0.x + a0.y*q0.y + a0.z*q0.z + a0.w*q0.w
               + a1.x*q1.x + a1.y*q1.y + a1.z*q1.z + a1.w*q1.w
               + a2.x*q2.x + a2.y*q2.y + a2.z*q2.z + a2.w*q2.w
               + a3.x*q3.x + a3.y*q3.y + a3.z*q3.z + a3.w*q3.w;
    float n2A  = a0.x*a0.x + a0.y*a0.y + a0.z*a0.z + a0.w*a0.w
               + a1.x*a1.x + a1.y*a1.y + a1.z*a1.z + a1.w*a1.w
               + a2.x*a2.x + a2.y*a2.y + a2.z*a2.z + a2.w*a2.w
               + a3.x*a3.x + a3.y*a3.y + a3.z*a3.z + a3.w*a3.w;
    float dotB = b0.x*q0.x + b0.y*q0.y + b0.z*q0.z + b0.w*q0.w
               + b1.x*q1.x + b1.y*q1.y + b1.z*q1.z + b1.w*q1.w
               + b2.x*q2.x + b2.y*q2.y + b2.z*q2.z + b2.w*q2.w
               + b3.x*q3.x + b3.y*q3.y + b3.z*q3.z + b3.w*q3.w;
    float n2B  = b0.x*b0.x + b0.y*b0.y + b0.z*b0.z + b0.w*b0.w
               + b1.x*b1.x + b1.y*b1.y + b1.z*b1.z + b1.w*b1.w
               + b2.x*b2.x + b2.y*b2.y + b2.z*b2.z + b2.w*b2.w
               + b3.x*b3.x + b3.y*b3.y + b3.z*b3.z + b3.w*b3.w;

#pragma unroll
    for (int off = 16; off; off >>= 1) {
        dotA += __shfl_down_sync(0xFFFFFFFFu, dotA, off);
        n2A  += __shfl_down_sync(0xFFFFFFFFu, n2A, off);
        dotB += __shfl_down_sync(0xFFFFFFFFu, dotB, off);
        n2B  += __shfl_down_sync(0xFFFFFFFFu, n2B, off);
    }
    if (lane == 0) {
        g_keys[r0] = f2key(dotA / fmaxf(sqrtf(n2A), 1e-8f));
        if (has1) g_keys[r0 + 1] = f2key(dotB / fmaxf(sqrtf(n2B), 1e-8f));
    }
}

// ---------------- select: hist -> barrier -> scan -> collect -> final ------
__global__ __launch_bounds__(256) void select_kernel(
        const float* __restrict__ q, float* __restrict__ out,
        int N, int K, int nblocks) {
    // 32KB shared, reused: phase1-2 hist = sbuf[0..2047];
    // phase4 sk = sbuf[0..SH_CAP-1], si = sbuf[SH_CAP..2*SH_CAP-1]
    __shared__ unsigned int sbuf[2 * SH_CAP];
    unsigned int* sh = sbuf;
    int t = threadIdx.x;
    for (int i = t; i < 2048; i += blockDim.x) sh[i] = 0;
    __syncthreads();

    // ---- phase 1: histogram of top 11 key bits ----
    int n4 = N >> 2;
    const uint4* k4 = (const uint4*)g_keys;
    for (int i = blockIdx.x * blockDim.x + t; i < n4; i += gridDim.x * blockDim.x) {
        uint4 k = k4[i];
        atomicAdd(&sh[k.x >> 21], 1u);
        atomicAdd(&sh[k.y >> 21], 1u);
        atomicAdd(&sh[k.z >> 21], 1u);
        atomicAdd(&sh[k.w >> 21], 1u);
    }
    if (blockIdx.x == 0) {
        for (int i = (n4 << 2) + t; i < N; i += blockDim.x)
            atomicAdd(&sh[g_keys[i] >> 21], 1u);
    }
    __syncthreads();
    for (int i = t; i < 2048; i += blockDim.x)
        if (sh[i]) atomicAdd(&g_hist1[i], sh[i]);

    // ---- grid barrier (co-residency: 296 blocks, >=6/SM capacity) ----
    grid_barrier(nblocks);

    // ---- phase 2: every block computes the threshold bin ----
    __shared__ unsigned int s_sel;
    __shared__ unsigned int wsum[8];
    {
        int base = 2047 - t * 8;   // thread t owns 8 descending bins
        unsigned int c[8];
        unsigned int s = 0;
#pragma unroll
        for (int j = 0; j < 8; j++) { c[j] = g_hist1[base - j]; s += c[j]; }

        int lane = t & 31;
        int w = t >> 5;
        unsigned int incl = s;
#pragma unroll
        for (int off = 1; off < 32; off <<= 1) {
            unsigned int v = __shfl_up_sync(0xFFFFFFFFu, incl, off);
            if (lane >= off) incl += v;
        }
        if (lane == 31) wsum[w] = incl;
        __syncthreads();
        if (t < 8) {
            unsigned int v = wsum[t];
#pragma unroll
            for (int off = 1; off < 8; off <<= 1) {
                unsigned int u = __shfl_up_sync(0xFFu, v, off);
                if (t >= off) v += u;
            }
            wsum[t] = v;
        }
        __syncthreads();
        unsigned int before = incl - s + (w > 0 ? wsum[w - 1] : 0u);
        unsigned int after  = before + s;
        unsigned int need = (unsigned int)K;
        if (before < need && after >= need) {
            unsigned int cum = before;
#pragma unroll
            for (int j = 0; j < 8; j++) {
                cum += c[j];
                if (cum >= need) { s_sel = (unsigned int)(base - j); break; }
            }
        }
        __syncthreads();
    }
    unsigned int sel = s_sel;

    // ---- phase 3: collect candidates ----
    for (int i = blockIdx.x * blockDim.x + t; i < n4; i += gridDim.x * blockDim.x) {
        uint4 k = k4[i];
        int base = i << 2;
        if ((k.x >> 21) >= sel) {
            unsigned int p = atomicAdd(&g_ncand, 1u);
            if (p < CAND_CAP) { g_cand_key[p] = k.x; g_cand_idx[p] = base; }
        }
        if ((k.y >> 21) >= sel) {
            unsigned int p = atomicAdd(&g_ncand, 1u);
            if (p < CAND_CAP) { g_cand_key[p] = k.y; g_cand_idx[p] = base + 1; }
        }
        if ((k.z >> 21) >= sel) {
            unsigned int p = atomicAdd(&g_ncand, 1u);
            if (p < CAND_CAP) { g_cand_key[p] = k.z; g_cand_idx[p] = base + 2; }
        }
        if ((k.w >> 21) >= sel) {
            unsigned int p = atomicAdd(&g_ncand, 1u);
            if (p < CAND_CAP) { g_cand_key[p] = k.w; g_cand_idx[p] = base + 3; }
        }
    }
    if (blockIdx.x == 0) {
        for (int i = (n4 << 2) + t; i < N; i += blockDim.x) {
            unsigned int key = g_keys[i];
            if ((key >> 21) >= sel) {
                unsigned int p = atomicAdd(&g_ncand, 1u);
                if (p < CAND_CAP) { g_cand_key[p] = key; g_cand_idx[p] = (unsigned int)i; }
            }
        }
    }

    // ---- phase 4: last finishing block ranks + writes + self-cleans ----
    __shared__ bool lastb;
    __threadfence();
    if (t == 0) lastb = (atomicAdd(&g_cfdone, 1u) == (unsigned int)nblocks - 1);
    __syncthreads();
    if (!lastb) return;

    int lane = t & 31;
    int w = t >> 5;

    // 1/|q|
    __shared__ float qs[8];
    __shared__ float qinv;
    float acc = 0.f;
    for (int i = t; i < D; i += blockDim.x) { float v = q[i]; acc += v * v; }
#pragma unroll
    for (int off = 16; off; off >>= 1) acc += __shfl_down_sync(0xFFFFFFFFu, acc, off);
    if (lane == 0) qs[w] = acc;
    __syncthreads();
    if (t == 0) {
        float s = 0.f;
#pragma unroll
        for (int i = 0; i < 8; i++) s += qs[i];
        qinv = 1.0f / fmaxf(sqrtf(s), 1e-8f);
    }

    // reuse sbuf for candidate staging (hist no longer needed)
    unsigned int* sk = sbuf;
    unsigned int* si = sbuf + SH_CAP;
    unsigned int n = g_ncand;
    if (n > CAND_CAP) n = CAND_CAP;
    bool use_sh = (n <= SH_CAP);
    __syncthreads();   // everyone done reading sbuf-as-hist
    if (use_sh) {
        for (unsigned int i = t; i < n; i += blockDim.x) {
            sk[i] = g_cand_key[i];
            si[i] = g_cand_idx[i];
        }
    }
    __syncthreads();

    for (unsigned int c = t; c < n; c += blockDim.x) {
        unsigned int key = use_sh ? sk[c] : g_cand_key[c];
        unsigned int idx = use_sh ? si[c] : g_cand_idx[c];
        unsigned int rank = 0;
        if (use_sh) {
            for (unsigned int j = 0; j < n; j++) {
                unsigned int kj = sk[j];
                if (kj > key || (kj == key && si[j] < idx)) rank++;
            }
        } else {
            for (unsigned int j = 0; j < n; j++) {
                unsigned int kj = g_cand_key[j];
                if (kj > key || (kj == key && g_cand_idx[j] < idx)) rank++;
            }
        }
        if (rank < (unsigned int)K) {
            out[rank]     = key2f(key) * qinv;
            out[K + rank] = (float)idx;
        }
    }
    __syncthreads();
    // self-clean for next graph replay
    for (int i = t; i < 2048; i += blockDim.x) g_hist1[i] = 0;
    if (t == 0) { g_ncand = 0; g_cfdone = 0; }
}

// ---------------------------------------------------------------------------
extern "C" void kernel_launch(void* const* d_in, const int* in_sizes, int n_in,
                              void* d_out, int out_size) {
    const float* q  = (const float*)d_in[0];
    const float* db = (const float*)d_in[1];
    int N = in_sizes[1] / D;
    int K = out_size / 2;   // values + indices
    float* out = (float*)d_out;

    int selBlocks = SEL_BLOCKS;            // 2/SM: co-resident with margin
    int simsBlocks = (N + 15) / 16;        // 8 warps, 2 rows/warp

    sims_kernel<<<simsBlocks, 256>>>(db, q, N);
    select_kernel<<<selBlocks, 256>>>(q, out, N, K, selBlocks);
}

// round 9
// speedup vs baseline: 1.0316x; 1.0134x over previous
#include <cuda_runtime.h>
#include <cuda_bf16.h>
#include <math.h>

// ---------------------------------------------------------------------------
// SearchNet: cosine similarity top-k
//   query [512] f32, database [N,512] f32 (N=500000), top_num=100
//   out: [values(K) | indices-as-float(K)] where K = out_size/2
//
// Pipeline (2 kernels):
//   sims   : dot(q_raw,d)/|d| -> sortable keys (order invariant under 1/|q|).
//   select : ONE kernel, software grid barriers. Residency proof: 592 blocks
//            (4/SM on >=148 SMs), 256 thr, 32KB smem -> capacity/SM =
//            min(smem 228/33=6, regs 65536/(33*256)=7, warps 64/8=8) = 6 >= 4.
//            phase 1: smem-agg 2048-bin histogram  ---- barrier ----
//            phase 2: per-block threshold scan
//            phase 3: collect candidates           ---- barrier ----
//            phase 4: grid-parallel exact rank (u64-packed, smem-staged),
//                     write top-K, distributed self-clean.
// ---------------------------------------------------------------------------

#define D 512
#define MAXN (1 << 20)        // >= 500000
#define CAND_CAP 16384
#define SH_CAP 4096           // candidates staged in reused 32KB smem
#define SEL_BLOCKS 592        // 4 per SM; co-resident (capacity 6/SM)

__device__ unsigned int g_keys[MAXN];
__device__ unsigned int g_hist1[2048];              // zeroed at load + self-clean
__device__ unsigned int g_bar_count;
__device__ volatile unsigned int g_bar_gen;
__device__ unsigned int g_ncand;
__device__ unsigned int g_cfdone;
__device__ unsigned int g_cand_key[CAND_CAP];
__device__ unsigned int g_cand_idx[CAND_CAP];

// float -> order-preserving uint
__device__ __forceinline__ unsigned int f2key(float f) {
    unsigned int u = __float_as_uint(f);
    return (u & 0x80000000u) ? ~u : (u | 0x80000000u);
}
__device__ __forceinline__ float key2f(unsigned int k) {
    unsigned int u = (k & 0x80000000u) ? (k ^ 0x80000000u) : ~k;
    return __uint_as_float(u);
}

// grid-wide spin barrier: ONLY valid when all blocks are co-resident.
__device__ __forceinline__ void grid_barrier(int nblocks) {
    __syncthreads();
    if (threadIdx.x == 0) {
        unsigned int gen = g_bar_gen;
        __threadfence();
        if (atomicAdd(&g_bar_count, 1u) == (unsigned int)nblocks - 1) {
            g_bar_count = 0;
            __threadfence();
            g_bar_gen = gen + 1;
        } else {
            while (g_bar_gen == gen) __nanosleep(32);
        }
    }
    __syncthreads();
    __threadfence();
}

// ---------------- sims: dot(q,d)/|d|, 2 rows per warp ----------------------
__global__ __launch_bounds__(256) void sims_kernel(const float* __restrict__ db,
                                                   const float* __restrict__ q,
                                                   int N) {
    int warp = (blockIdx.x * blockDim.x + threadIdx.x) >> 5;
    int lane = threadIdx.x & 31;
    int r0 = warp * 2;
    if (r0 >= N) return;
    bool has1 = (r0 + 1) < N;

    const float4* q4 = (const float4*)q;
    float4 q0 = __ldg(&q4[lane]);
    float4 q1 = __ldg(&q4[lane + 32]);
    float4 q2 = __ldg(&q4[lane + 64]);
    float4 q3 = __ldg(&q4[lane + 96]);

    const float4* rowA = (const float4*)(db + (size_t)r0 * D);
    const float4* rowB = (const float4*)(db + (size_t)(r0 + (has1 ? 1 : 0)) * D);

    // front-batch 8 independent streaming DRAM loads (touch-once data)
    float4 a0 = __ldcs(&rowA[lane]);
    float4 a1 = __ldcs(&rowA[lane + 32]);
    float4 a2 = __ldcs(&rowA[lane + 64]);
    float4 a3 = __ldcs(&rowA[lane + 96]);
    float4 b0 = __ldcs(&rowB[lane]);
    float4 b1 = __ldcs(&rowB[lane + 32]);
    float4 b2 = __ldcs(&rowB[lane + 64]);
    float4 b3 = __ldcs(&rowB[lane + 96]);

    float dotA = a0.x*q0.x + a0.y*q0.y + a0.z*q0.z + a0.w*q0.w
               + a1.x*q1.x + a1.y*q1.y + a1.z*q1.z + a1.w*q1.w
               + a2.x*q2.x + a2.y*q2.y + a2.z*q2.z + a2.w*q2.w
               + a3.x*q3.x + a3.y*q3.y + a3.z*q3.z + a3.w*q3.w;
    float n2A  = a0.x*a0.x + a0.y*a0.y + a0.z*a0.z + a0.w*a0.w
               + a1.x*a1.x + a1.y*a1.y + a1.z*a1.z + a1.w*a1.w
               + a2.x*a2.x + a2.y*a2.y + a2.z*a2.z + a2.w*a2.w
               + a3.x*a3.x + a3.y*a3.y + a3.z*a3.z + a3.w*a3.w;
    float dotB = b0.x*q0.x + b0.y*q0.y + b0.z*q0.z + b0.w*q0.w
               + b1.x*q1.x + b1.y*q1.y + b1.z*q1.z + b1.w*q1.w
               + b2.x*q2.x + b2.y*q2.y + b2.z*q2.z + b2.w*q2.w
               + b3.x*q3.x + b3.y*q3.y + b3.z*q3.z + b3.w*q3.w;
    float n2B  = b0.x*b0.x + b0.y*b0.y + b0.z*b0.z + b0.w*b0.w
               + b1.x*b1.x + b1.y*b1.y + b1.z*b1.z + b1.w*b1.w
               + b2.x*b2.x + b2.y*b2.y + b2.z*b2.z + b2.w*b2.w
               + b3.x*b3.x + b3.y*b3.y + b3.z*b3.z + b3.w*b3.w;

#pragma unroll
    for (int off = 16; off; off >>= 1) {
        dotA += __shfl_down_sync(0xFFFFFFFFu, dotA, off);
        n2A  += __shfl_down_sync(0xFFFFFFFFu, n2A, off);
        dotB += __shfl_down_sync(0xFFFFFFFFu, dotB, off);
        n2B  += __shfl_down_sync(0xFFFFFFFFu, n2B, off);
    }
    if (lane == 0) {
        g_keys[r0] = f2key(dotA / fmaxf(sqrtf(n2A), 1e-8f));
        if (has1) g_keys[r0 + 1] = f2key(dotB / fmaxf(sqrtf(n2B), 1e-8f));
    }
}

// ---------------- select ---------------------------------------------------
__global__ __launch_bounds__(256) void select_kernel(
        const float* __restrict__ q, float* __restrict__ out,
        int N, int K, int nblocks) {
    // 32KB shared, reused: phase1-2 hist = sbuf[0..2047] (uint);
    // phase4: packed u64 candidates sck[0..SH_CAP-1]
    __shared__ unsigned int sbuf[2 * SH_CAP];
    unsigned int* sh = sbuf;
    int t = threadIdx.x;
    int gtid = blockIdx.x * blockDim.x + t;
    for (int i = t; i < 2048; i += blockDim.x) sh[i] = 0;
    __syncthreads();

    // ---- phase 1: histogram of top 11 key bits ----
    int n4 = N >> 2;
    const uint4* k4 = (const uint4*)g_keys;
    for (int i = gtid; i < n4; i += gridDim.x * blockDim.x) {
        uint4 k = k4[i];
        atomicAdd(&sh[k.x >> 21], 1u);
        atomicAdd(&sh[k.y >> 21], 1u);
        atomicAdd(&sh[k.z >> 21], 1u);
        atomicAdd(&sh[k.w >> 21], 1u);
    }
    if (blockIdx.x == 0) {
        for (int i = (n4 << 2) + t; i < N; i += blockDim.x)
            atomicAdd(&sh[g_keys[i] >> 21], 1u);
    }
    __syncthreads();
    for (int i = t; i < 2048; i += blockDim.x)
        if (sh[i]) atomicAdd(&g_hist1[i], sh[i]);

    grid_barrier(nblocks);

    // ---- phase 2: every block computes the threshold bin ----
    __shared__ unsigned int s_sel;
    __shared__ unsigned int wsum[8];
    {
        int base = 2047 - t * 8;   // thread t owns 8 descending bins
        unsigned int c[8];
        unsigned int s = 0;
#pragma unroll
        for (int j = 0; j < 8; j++) { c[j] = g_hist1[base - j]; s += c[j]; }

        int lane = t & 31;
        int w = t >> 5;
        unsigned int incl = s;
#pragma unroll
        for (int off = 1; off < 32; off <<= 1) {
            unsigned int v = __shfl_up_sync(0xFFFFFFFFu, incl, off);
            if (lane >= off) incl += v;
        }
        if (lane == 31) wsum[w] = incl;
        __syncthreads();
        if (t < 8) {
            unsigned int v = wsum[t];
#pragma unroll
            for (int off = 1; off < 8; off <<= 1) {
                unsigned int u = __shfl_up_sync(0xFFu, v, off);
                if (t >= off) v += u;
            }
            wsum[t] = v;
        }
        __syncthreads();
        unsigned int before = incl - s + (w > 0 ? wsum[w - 1] : 0u);
        unsigned int after  = before + s;
        unsigned int need = (unsigned int)K;
        if (before < need && after >= need) {
            unsigned int cum = before;
#pragma unroll
            for (int j = 0; j < 8; j++) {
                cum += c[j];
                if (cum >= need) { s_sel = (unsigned int)(base - j); break; }
            }
        }
        __syncthreads();
    }
    unsigned int sel = s_sel;

    // ---- phase 3: collect candidates ----
    for (int i = gtid; i < n4; i += gridDim.x * blockDim.x) {
        uint4 k = k4[i];
        int base = i << 2;
        if ((k.x >> 21) >= sel) {
            unsigned int p = atomicAdd(&g_ncand, 1u);
            if (p < CAND_CAP) { g_cand_key[p] = k.x; g_cand_idx[p] = base; }
        }
        if ((k.y >> 21) >= sel) {
            unsigned int p = atomicAdd(&g_ncand, 1u);
            if (p < CAND_CAP) { g_cand_key[p] = k.y; g_cand_idx[p] = base + 1; }
        }
        if ((k.z >> 21) >= sel) {
            unsigned int p = atomicAdd(&g_ncand, 1u);
            if (p < CAND_CAP) { g_cand_key[p] = k.z; g_cand_idx[p] = base + 2; }
        }
        if ((k.w >> 21) >= sel) {
            unsigned int p = atomicAdd(&g_ncand, 1u);
            if (p < CAND_CAP) { g_cand_key[p] = k.w; g_cand_idx[p] = base + 3; }
        }
    }
    if (blockIdx.x == 0) {
        for (int i = (n4 << 2) + t; i < N; i += blockDim.x) {
            unsigned int key = g_keys[i];
            if ((key >> 21) >= sel) {
                unsigned int p = atomicAdd(&g_ncand, 1u);
                if (p < CAND_CAP) { g_cand_key[p] = key; g_cand_idx[p] = (unsigned int)i; }
            }
        }
    }

    grid_barrier(nblocks);

    // ---- phase 4: grid-parallel exact rank ----
    unsigned int n = g_ncand;
    if (n > CAND_CAP) n = CAND_CAP;

    // distributed hist re-zero for next replay (reads finished in phase 2)
    if (gtid < 2048) g_hist1[gtid] = 0;

    // blocks whose thread range overlaps [0, n) participate in ranking
    unsigned int blk_lo = blockIdx.x * blockDim.x;
    if (blk_lo < n) {
        // 1/|q| (redundant per ranking block; L2-hot)
        __shared__ float qs[8];
        __shared__ float qinv;
        {
            int lane = t & 31;
            int w = t >> 5;
            float acc = 0.f;
            for (int i = t; i < D; i += blockDim.x) { float v = q[i]; acc += v * v; }
#pragma unroll
            for (int off = 16; off; off >>= 1)
                acc += __shfl_down_sync(0xFFFFFFFFu, acc, off);
            if (lane == 0) qs[w] = acc;
            __syncthreads();
            if (t == 0) {
                float s = 0.f;
#pragma unroll
                for (int i = 0; i < 8; i++) s += qs[i];
                qinv = 1.0f / fmaxf(sqrtf(s), 1e-8f);
            }
            __syncthreads();
        }

        if (n <= SH_CAP) {
            // stage packed candidates in reused smem: higher pack = better,
            // ties broken toward LOWER index via ~idx in low word.
            unsigned long long* sck = (unsigned long long*)sbuf;
            for (unsigned int i = t; i < n; i += blockDim.x)
                sck[i] = ((unsigned long long)g_cand_key[i] << 32)
                       | (unsigned long long)(~g_cand_idx[i]);
            __syncthreads();
            unsigned int c = blk_lo + t;
            if (c < n) {
                unsigned long long me = sck[c];
                unsigned int rank = 0;
                for (unsigned int j = 0; j < n; j++)
                    if (sck[j] > me) rank++;
                if (rank < (unsigned int)K) {
                    out[rank]     = key2f((unsigned int)(me >> 32)) * qinv;
                    out[K + rank] = (float)(~(unsigned int)me);
                }
            }
        } else {
            // fallback: global-memory ranking (degenerate distributions)
            unsigned int c = blk_lo + t;
            if (c < n) {
                unsigned int key = g_cand_key[c];
                unsigned int idx = g_cand_idx[c];
                unsigned int rank = 0;
                for (unsigned int j = 0; j < n; j++) {
                    unsigned int kj = g_cand_key[j];
                    if (kj > key || (kj == key && g_cand_idx[j] < idx)) rank++;
                }
                if (rank < (unsigned int)K) {
                    out[rank]     = key2f(key) * qinv;
                    out[K + rank] = (float)idx;
                }
            }
        }
    }

    // ---- last finishing block resets scalars for next replay ----
    __shared__ bool lastb;
    __threadfence();
    if (t == 0) lastb = (atomicAdd(&g_cfdone, 1u) == (unsigned int)nblocks - 1);
    __syncthreads();
    if (lastb && t == 0) { g_ncand = 0; g_cfdone = 0; }
}

// ---------------------------------------------------------------------------
extern "C" void kernel_launch(void* const* d_in, const int* in_sizes, int n_in,
                              void* d_out, int out_size) {
    const float* q  = (const float*)d_in[0];
    const float* db = (const float*)d_in[1];
    int N = in_sizes[1] / D;
    int K = out_size / 2;   // values + indices
    float* out = (float*)d_out;

    int selBlocks = SEL_BLOCKS;            // 4/SM: co-resident (capacity 6/SM)
    int simsBlocks = (N + 15) / 16;        // 8 warps, 2 rows/warp

    sims_kernel<<<simsBlocks, 256>>>(db, q, N);
    select_kernel<<<selBlocks, 256>>>(q, out, N, K, selBlocks);
}